// round 2
// baseline (speedup 1.0000x reference)
#include <cuda_runtime.h>
#include <math.h>

// Problem constants (fixed by the reference)
#define TT   2048      // total tokens (2*1024)
#define HD   2048      // hidden dim
#define ID   5632      // intermediate dim
#define NE   8         // experts
// top-k = 2

// ---------------- device scratch (no allocations allowed) ----------------
__device__ int   g_count[NE];                         // tokens routed per expert
__device__ int   g_tok[NE * TT];                      // token id per expert slot
__device__ float g_wt [NE * TT];                      // combine weight per expert slot
__device__ float g_act[(size_t)NE * TT * ID];         // silu(g)*u activations per slot

// ---------------- router: logits -> top2 -> renorm -> scatter ----------------
__global__ void route_kernel(const float* __restrict__ x,
                             const float* __restrict__ gw) {
    const int t   = blockIdx.x;
    const int tid = threadIdx.x;   // 128 threads

    float p[NE];
#pragma unroll
    for (int e = 0; e < NE; e++) p[e] = 0.f;

    const float* xr = x + (size_t)t * HD;
    for (int h = tid; h < HD; h += 128) {
        float xv = xr[h];
#pragma unroll
        for (int e = 0; e < NE; e++) p[e] += xv * gw[e * HD + h];
    }

    __shared__ float sh[NE][128];
#pragma unroll
    for (int e = 0; e < NE; e++) sh[e][tid] = p[e];
    __syncthreads();
    for (int off = 64; off > 0; off >>= 1) {
        if (tid < off) {
#pragma unroll
            for (int e = 0; e < NE; e++) sh[e][tid] += sh[e][tid + off];
        }
        __syncthreads();
    }

    if (tid == 0) {
        float l[NE];
#pragma unroll
        for (int e = 0; e < NE; e++) l[e] = sh[e][0];
        // top-1 (first max on ties, matching jax.lax.top_k tie-break)
        int i0 = 0;
#pragma unroll
        for (int e = 1; e < NE; e++) if (l[e] > l[i0]) i0 = e;
        // top-2
        int i1 = (i0 == 0) ? 1 : 0;
#pragma unroll
        for (int e = 0; e < NE; e++) if (e != i0 && l[e] > l[i1]) i1 = e;

        // renormalized top-2 softmax: denominators cancel
        float d  = expf(l[i1] - l[i0]);         // <= 1
        float w0 = 1.f / (1.f + d);
        float w1 = d / (1.f + d);

        int p0 = atomicAdd(&g_count[i0], 1);
        g_tok[i0 * TT + p0] = t;  g_wt[i0 * TT + p0] = w0;
        int p1 = atomicAdd(&g_count[i1], 1);
        g_tok[i1 * TT + p1] = t;  g_wt[i1 * TT + p1] = w1;
    }
}

// ---------------- GEMM1: act = silu(x@w1^T) * (x@w3^T) per expert ----------------
// tile 64x64x16, 256 threads, 4x4 per thread, two accumulators (gate & up)
__global__ __launch_bounds__(256)
void gemm1_kernel(const float* __restrict__ x,
                  const float* __restrict__ w1,
                  const float* __restrict__ w3) {
    const int e   = blockIdx.z;
    const int cnt = g_count[e];
    const int m0  = blockIdx.y * 64;
    if (m0 >= cnt) return;                 // empty row tile for this expert
    const int n0  = blockIdx.x * 64;

    __shared__ float xs [16][64];
    __shared__ float w1s[16][64];
    __shared__ float w3s[16][64];

    const int tid = threadIdx.x;
    const int lm  = tid >> 2;              // 0..63  (row within tile for loads)
    const int lc  = (tid & 3) * 4;         // 0,4,8,12 (k offset, float4)

    int tok = -1;
    if (m0 + lm < cnt) tok = g_tok[e * TT + m0 + lm];
    const float* xrow  = (tok >= 0) ? (x + (size_t)tok * HD) : x;
    const float* w1row = w1 + ((size_t)e * ID + n0 + lm) * HD;
    const float* w3row = w3 + ((size_t)e * ID + n0 + lm) * HD;

    const int tm = (tid >> 4) * 4;         // 0..60 output row base
    const int tn = (tid & 15) * 4;         // 0..60 output col base

    float ag[4][4] = {{0.f}};
    float au[4][4] = {{0.f}};

    for (int k0 = 0; k0 < HD; k0 += 16) {
        float4 xv = make_float4(0.f, 0.f, 0.f, 0.f);
        if (tok >= 0) xv = *(const float4*)(xrow + k0 + lc);
        float4 av = *(const float4*)(w1row + k0 + lc);
        float4 bv = *(const float4*)(w3row + k0 + lc);

        xs [lc + 0][lm] = xv.x; xs [lc + 1][lm] = xv.y;
        xs [lc + 2][lm] = xv.z; xs [lc + 3][lm] = xv.w;
        w1s[lc + 0][lm] = av.x; w1s[lc + 1][lm] = av.y;
        w1s[lc + 2][lm] = av.z; w1s[lc + 3][lm] = av.w;
        w3s[lc + 0][lm] = bv.x; w3s[lc + 1][lm] = bv.y;
        w3s[lc + 2][lm] = bv.z; w3s[lc + 3][lm] = bv.w;
        __syncthreads();

#pragma unroll
        for (int kk = 0; kk < 16; kk++) {
            float a[4], b[4], c[4];
            *(float4*)a = *(const float4*)&xs [kk][tm];
            *(float4*)b = *(const float4*)&w1s[kk][tn];
            *(float4*)c = *(const float4*)&w3s[kk][tn];
#pragma unroll
            for (int i = 0; i < 4; i++)
#pragma unroll
                for (int j = 0; j < 4; j++) {
                    ag[i][j] += a[i] * b[j];
                    au[i][j] += a[i] * c[j];
                }
        }
        __syncthreads();
    }

#pragma unroll
    for (int i = 0; i < 4; i++) {
        const int m = m0 + tm + i;
        if (m < cnt) {
            float v[4];
#pragma unroll
            for (int j = 0; j < 4; j++) {
                float g = ag[i][j];
                float s = g / (1.f + expf(-g));   // silu
                v[j] = s * au[i][j];
            }
            *(float4*)&g_act[(size_t)(e * TT + m) * ID + n0 + tn] =
                make_float4(v[0], v[1], v[2], v[3]);
        }
    }
}

// ---------------- GEMM2: out[tok] += w * (act @ w2^T) per expert ----------------
__global__ __launch_bounds__(256)
void gemm2_kernel(const float* __restrict__ w2,
                  float* __restrict__ out) {
    const int e   = blockIdx.z;
    const int cnt = g_count[e];
    const int m0  = blockIdx.y * 64;
    if (m0 >= cnt) return;
    const int n0  = blockIdx.x * 64;

    __shared__ float as[16][64];
    __shared__ float ws[16][64];

    const int tid = threadIdx.x;
    const int lm  = tid >> 2;
    const int lc  = (tid & 3) * 4;
    const bool mvalid = (m0 + lm < cnt);

    const float* arow = g_act + (size_t)(e * TT + m0 + lm) * ID;
    const float* wrow = w2 + ((size_t)e * HD + n0 + lm) * ID;

    const int tm = (tid >> 4) * 4;
    const int tn = (tid & 15) * 4;

    float acc[4][4] = {{0.f}};

    for (int k0 = 0; k0 < ID; k0 += 16) {
        float4 av = make_float4(0.f, 0.f, 0.f, 0.f);
        if (mvalid) av = *(const float4*)(arow + k0 + lc);
        float4 wv = *(const float4*)(wrow + k0 + lc);

        as[lc + 0][lm] = av.x; as[lc + 1][lm] = av.y;
        as[lc + 2][lm] = av.z; as[lc + 3][lm] = av.w;
        ws[lc + 0][lm] = wv.x; ws[lc + 1][lm] = wv.y;
        ws[lc + 2][lm] = wv.z; ws[lc + 3][lm] = wv.w;
        __syncthreads();

#pragma unroll
        for (int kk = 0; kk < 16; kk++) {
            float a[4], b[4];
            *(float4*)a = *(const float4*)&as[kk][tm];
            *(float4*)b = *(const float4*)&ws[kk][tn];
#pragma unroll
            for (int i = 0; i < 4; i++)
#pragma unroll
                for (int j = 0; j < 4; j++)
                    acc[i][j] += a[i] * b[j];
        }
        __syncthreads();
    }

#pragma unroll
    for (int i = 0; i < 4; i++) {
        const int m = m0 + tm + i;
        if (m < cnt) {
            const int   tok = g_tok[e * TT + m];
            const float w   = g_wt [e * TT + m];
#pragma unroll
            for (int j = 0; j < 4; j++)
                atomicAdd(&out[(size_t)tok * HD + n0 + tn + j], w * acc[i][j]);
        }
    }
}

// ---------------- launch ----------------
extern "C" void kernel_launch(void* const* d_in, const int* in_sizes, int n_in,
                              void* d_out, int out_size) {
    const float* x  = (const float*)d_in[0];   // hidden_states [2,1024,2048]
    const float* gw = (const float*)d_in[1];   // gate_w  [E,H]
    const float* w1 = (const float*)d_in[2];   // w1 [E,I,H]
    const float* w3 = (const float*)d_in[3];   // w3 [E,I,H]
    const float* w2 = (const float*)d_in[4];   // w2 [E,H,I]
    float* out = (float*)d_out;

    void* cnt_addr = nullptr;
    cudaGetSymbolAddress(&cnt_addr, g_count);
    cudaMemsetAsync(cnt_addr, 0, sizeof(int) * NE, 0);
    cudaMemsetAsync(d_out, 0, sizeof(float) * (size_t)out_size, 0);

    route_kernel<<<TT, 128>>>(x, gw);

    dim3 g1(ID / 64, TT / 64, NE);
    gemm1_kernel<<<g1, 256>>>(x, w1, w3);

    dim3 g2(HD / 64, TT / 64, NE);
    gemm2_kernel<<<g2, 256>>>(w2, out);
}

// round 4
// speedup vs baseline: 3.1316x; 3.1316x over previous
#include <cuda_runtime.h>
#include <cuda_bf16.h>
#include <math.h>
#include <stdint.h>

// Problem constants
#define TT   2048      // tokens
#define HD   2048      // hidden
#define ID   5632      // intermediate
#define NE   8         // experts
#define KC   64        // K-chunk (bf16 elems) = 128B row

// ---------------- device scratch ----------------
__device__ int   g_count[NE];
__device__ int   g_tok[NE * TT];
__device__ float g_wt [NE * TT];

#define WSZ (NE * (size_t)ID * HD)
__device__ __nv_bfloat16 g_w1h[WSZ];
__device__ __nv_bfloat16 g_w1l[WSZ];
__device__ __nv_bfloat16 g_w3h[WSZ];
__device__ __nv_bfloat16 g_w3l[WSZ];
__device__ __nv_bfloat16 g_w2h[WSZ];
__device__ __nv_bfloat16 g_w2l[WSZ];
__device__ __nv_bfloat16 g_xh [(size_t)TT * HD];
__device__ __nv_bfloat16 g_xl [(size_t)TT * HD];
__device__ __nv_bfloat16 g_ah [NE * (size_t)TT * ID];
__device__ __nv_bfloat16 g_al [NE * (size_t)TT * ID];

// ---------------- helpers ----------------
__device__ __forceinline__ uint32_t smem_u32(const void* p) {
    return (uint32_t)__cvta_generic_to_shared(p);
}
#define SWZ(o) ((o) ^ (((o) >> 3) & 0x70))

__device__ __forceinline__ void cp16(uint32_t dst, const void* src, int sz) {
    asm volatile("cp.async.cg.shared.global [%0], [%1], 16, %2;"
                 :: "r"(dst), "l"(src), "r"(sz) : "memory");
}
#define CP_COMMIT() asm volatile("cp.async.commit_group;" ::: "memory")
#define CP_WAIT1()  asm volatile("cp.async.wait_group 1;" ::: "memory")

__device__ __forceinline__ void ldsm4(uint32_t* r, uint32_t addr) {
    asm volatile("ldmatrix.sync.aligned.m8n8.x4.shared.b16 {%0,%1,%2,%3}, [%4];"
                 : "=r"(r[0]), "=r"(r[1]), "=r"(r[2]), "=r"(r[3]) : "r"(addr));
}
__device__ __forceinline__ void mma_bf16(float* d, const uint32_t* a, const uint32_t* b) {
    asm volatile("mma.sync.aligned.m16n8k16.row.col.f32.bf16.bf16.f32 "
                 "{%0,%1,%2,%3}, {%4,%5,%6,%7}, {%8,%9}, {%0,%1,%2,%3};"
                 : "+f"(d[0]), "+f"(d[1]), "+f"(d[2]), "+f"(d[3])
                 : "r"(a[0]), "r"(a[1]), "r"(a[2]), "r"(a[3]),
                   "r"(b[0]), "r"(b[1]));
}

// A-fragment ldmatrix address (m16 x k16 at (mbase, kb*16) within 128B-row tile)
__device__ __forceinline__ uint32_t a_addr(uint32_t base, int mbase, int kb, int lane) {
    int row = mbase + ((lane >> 3) & 1) * 8 + (lane & 7);
    uint32_t off = (uint32_t)(row * 128 + kb * 32 + (lane >> 4) * 16);
    return base + SWZ(off);
}
// B-fragment ldmatrix address (n16 x k16 at (nbase, kb*16))
__device__ __forceinline__ uint32_t b_addr(uint32_t base, int nbase, int kb, int lane) {
    int row = nbase + ((lane >> 4) << 3) + (lane & 7);
    uint32_t off = (uint32_t)(row * 128 + kb * 32 + ((lane >> 3) & 1) * 16);
    return base + SWZ(off);
}

// ---------------- fp32 -> bf16 hi/lo split ----------------
__global__ void split_kernel(const float* __restrict__ src,
                             __nv_bfloat16* __restrict__ hi,
                             __nv_bfloat16* __restrict__ lo, int n4) {
    int i = blockIdx.x * blockDim.x + threadIdx.x;
    if (i >= n4) return;
    float4 v = ((const float4*)src)[i];
    __nv_bfloat16 h0 = __float2bfloat16(v.x), h1 = __float2bfloat16(v.y);
    __nv_bfloat16 h2 = __float2bfloat16(v.z), h3 = __float2bfloat16(v.w);
    __nv_bfloat16 l0 = __float2bfloat16(v.x - __bfloat162float(h0));
    __nv_bfloat16 l1 = __float2bfloat16(v.y - __bfloat162float(h1));
    __nv_bfloat16 l2 = __float2bfloat16(v.z - __bfloat162float(h2));
    __nv_bfloat16 l3 = __float2bfloat16(v.w - __bfloat162float(h3));
    __nv_bfloat162 hp0 = __halves2bfloat162(h0, h1), hp1 = __halves2bfloat162(h2, h3);
    __nv_bfloat162 lp0 = __halves2bfloat162(l0, l1), lp1 = __halves2bfloat162(l2, l3);
    uint2 hu, lu;
    hu.x = *(uint32_t*)&hp0; hu.y = *(uint32_t*)&hp1;
    lu.x = *(uint32_t*)&lp0; lu.y = *(uint32_t*)&lp1;
    ((uint2*)hi)[i] = hu;
    ((uint2*)lo)[i] = lu;
}

// ---------------- router ----------------
__global__ void route_kernel(const float* __restrict__ x,
                             const float* __restrict__ gw) {
    const int t   = blockIdx.x;
    const int tid = threadIdx.x;   // 128
    float p[NE];
#pragma unroll
    for (int e = 0; e < NE; e++) p[e] = 0.f;
    const float* xr = x + (size_t)t * HD;
    for (int h = tid; h < HD; h += 128) {
        float xv = xr[h];
#pragma unroll
        for (int e = 0; e < NE; e++) p[e] += xv * gw[e * HD + h];
    }
    __shared__ float sh[NE][128];
#pragma unroll
    for (int e = 0; e < NE; e++) sh[e][tid] = p[e];
    __syncthreads();
    for (int off = 64; off > 0; off >>= 1) {
        if (tid < off) {
#pragma unroll
            for (int e = 0; e < NE; e++) sh[e][tid] += sh[e][tid + off];
        }
        __syncthreads();
    }
    if (tid == 0) {
        float l[NE];
#pragma unroll
        for (int e = 0; e < NE; e++) l[e] = sh[e][0];
        int i0 = 0;
#pragma unroll
        for (int e = 1; e < NE; e++) if (l[e] > l[i0]) i0 = e;
        int i1 = (i0 == 0) ? 1 : 0;
#pragma unroll
        for (int e = 0; e < NE; e++) if (e != i0 && l[e] > l[i1]) i1 = e;
        float d  = expf(l[i1] - l[i0]);
        float w0 = 1.f / (1.f + d);
        float w1 = d / (1.f + d);
        int p0 = atomicAdd(&g_count[i0], 1);
        g_tok[i0 * TT + p0] = t;  g_wt[i0 * TT + p0] = w0;
        int p1 = atomicAdd(&g_count[i1], 1);
        g_tok[i1 * TT + p1] = t;  g_wt[i1 * TT + p1] = w1;
    }
}

// SMEM: [0..512) s_tok, [512..1024) s_wt, tiles from 1024, stage stride 64KB
#define STAGE_B 65536
#define SMEM_SZ (1024 + 2 * STAGE_B)

// ---------------- GEMM1: act = silu(x@w1^T) * (x@w3^T) ----------------
// CTA 128(M) x 64(N); 8 warps 4x2 of 32x32; dual accumulators.
__device__ __forceinline__ void g1_load(char* sb, const int* s_tok,
                                        int e, int n0, int k0, int tid) {
    char* xh = sb;            char* xl = sb + 16384;
    char* w1h = sb + 32768;   char* w1l = sb + 40960;
    char* w3h = sb + 49152;   char* w3l = sb + 57344;
#pragma unroll
    for (int it = 0; it < 4; it++) {
        int i = tid + it * 256;
        int row = i >> 3, c16 = i & 7;
        int tok = s_tok[row];
        uint32_t doff = SWZ((uint32_t)(row * 128 + c16 * 16));
        size_t goff = (size_t)(tok < 0 ? 0 : tok) * HD + k0 + c16 * 8;
        int sz = (tok < 0) ? 0 : 16;
        cp16(smem_u32(xh + doff), g_xh + goff, sz);
        cp16(smem_u32(xl + doff), g_xl + goff, sz);
    }
#pragma unroll
    for (int it = 0; it < 2; it++) {
        int i = tid + it * 256;
        int row = i >> 3, c16 = i & 7;
        uint32_t doff = SWZ((uint32_t)(row * 128 + c16 * 16));
        size_t goff = ((size_t)e * ID + n0 + row) * HD + k0 + c16 * 8;
        cp16(smem_u32(w1h + doff), g_w1h + goff, 16);
        cp16(smem_u32(w1l + doff), g_w1l + goff, 16);
        cp16(smem_u32(w3h + doff), g_w3h + goff, 16);
        cp16(smem_u32(w3l + doff), g_w3l + goff, 16);
    }
}

__global__ __launch_bounds__(256)
void gemm1_kernel() {
    extern __shared__ char smem[];
    const int e   = blockIdx.z;
    const int cnt = g_count[e];
    const int m0  = blockIdx.y * 128;
    if (m0 >= cnt) return;
    const int n0  = blockIdx.x * 64;
    const int tid  = threadIdx.x;
    const int wid  = tid >> 5, lane = tid & 31;

    int* s_tok = (int*)smem;
    if (tid < 128) {
        int m = m0 + tid;
        s_tok[tid] = (m < cnt) ? g_tok[e * TT + m] : -1;
    }
    __syncthreads();

    const int wm = (wid & 3) * 32;   // warp M offset
    const int wn = (wid >> 2) * 32;  // warp N offset

    float accg[2][4][4], accu[2][4][4];
#pragma unroll
    for (int mf = 0; mf < 2; mf++)
#pragma unroll
        for (int nf = 0; nf < 4; nf++)
#pragma unroll
            for (int r = 0; r < 4; r++) { accg[mf][nf][r] = 0.f; accu[mf][nf][r] = 0.f; }

    g1_load(smem + 1024, s_tok, e, n0, 0, tid);
    CP_COMMIT();

    const int NCH = HD / KC;   // 32
    for (int c = 0; c < NCH; c++) {
        if (c + 1 < NCH)
            g1_load(smem + 1024 + ((c + 1) & 1) * STAGE_B, s_tok, e, n0, (c + 1) * KC, tid);
        CP_COMMIT();
        CP_WAIT1();
        __syncthreads();

        char* sb = smem + 1024 + (c & 1) * STAGE_B;
        const uint32_t xh = smem_u32(sb),          xl  = xh + 16384;
        const uint32_t b1h = xh + 32768,           b1l = xh + 40960;
        const uint32_t b3h = xh + 49152,           b3l = xh + 57344;

#pragma unroll
        for (int kb = 0; kb < 4; kb++) {
            uint32_t ah[2][4], al[2][4];
#pragma unroll
            for (int mf = 0; mf < 2; mf++) {
                uint32_t aa = a_addr(0, wm + mf * 16, kb, lane);
                ldsm4(ah[mf], xh + aa);
                ldsm4(al[mf], xl + aa);
            }
            uint32_t r1h[2][4], r1l[2][4], r3h[2][4], r3l[2][4];
#pragma unroll
            for (int nf2 = 0; nf2 < 2; nf2++) {
                uint32_t ba = b_addr(0, wn + nf2 * 16, kb, lane);
                ldsm4(r1h[nf2], b1h + ba);
                ldsm4(r1l[nf2], b1l + ba);
                ldsm4(r3h[nf2], b3h + ba);
                ldsm4(r3l[nf2], b3l + ba);
            }
#pragma unroll
            for (int mf = 0; mf < 2; mf++)
#pragma unroll
                for (int nf = 0; nf < 4; nf++) {
                    const int h = nf >> 1, q = (nf & 1) * 2;
                    mma_bf16(accg[mf][nf], ah[mf], &r1h[h][q]);
                    mma_bf16(accg[mf][nf], ah[mf], &r1l[h][q]);
                    mma_bf16(accg[mf][nf], al[mf], &r1h[h][q]);
                    mma_bf16(accu[mf][nf], ah[mf], &r3h[h][q]);
                    mma_bf16(accu[mf][nf], ah[mf], &r3l[h][q]);
                    mma_bf16(accu[mf][nf], al[mf], &r3h[h][q]);
                }
        }
        __syncthreads();
    }

    // epilogue: silu(g)*u -> bf16 hi/lo act
#pragma unroll
    for (int mf = 0; mf < 2; mf++) {
#pragma unroll
        for (int rr = 0; rr < 2; rr++) {        // c01 (row) / c23 (row+8)
            const int slot = m0 + wm + mf * 16 + rr * 8 + (lane >> 2);
            if (slot >= cnt) continue;
            const size_t base = (size_t)(e * TT + slot) * ID + n0;
#pragma unroll
            for (int nf = 0; nf < 4; nf++) {
                float g0 = accg[mf][nf][rr * 2 + 0], g1 = accg[mf][nf][rr * 2 + 1];
                float u0 = accu[mf][nf][rr * 2 + 0], u1 = accu[mf][nf][rr * 2 + 1];
                float a0 = u0 * g0 / (1.f + __expf(-g0));
                float a1 = u1 * g1 / (1.f + __expf(-g1));
                __nv_bfloat16 h0 = __float2bfloat16(a0), h1 = __float2bfloat16(a1);
                __nv_bfloat16 l0 = __float2bfloat16(a0 - __bfloat162float(h0));
                __nv_bfloat16 l1 = __float2bfloat16(a1 - __bfloat162float(h1));
                const int col = wn + nf * 8 + (lane & 3) * 2;
                *(__nv_bfloat162*)(g_ah + base + col) = __halves2bfloat162(h0, h1);
                *(__nv_bfloat162*)(g_al + base + col) = __halves2bfloat162(l0, l1);
            }
        }
    }
}

// ---------------- GEMM2: out[tok] += wt * (act @ w2^T) ----------------
// CTA 128(M) x 128(N); 8 warps 2x4 of 64x32.
__device__ __forceinline__ void g2_load(char* sb, int e, int m0, int cnt,
                                        int n0, int k0, int tid) {
    char* ah = sb;           char* al = sb + 16384;
    char* wh = sb + 32768;   char* wl = sb + 49152;
#pragma unroll
    for (int it = 0; it < 4; it++) {
        int i = tid + it * 256;
        int row = i >> 3, c16 = i & 7;
        uint32_t doff = SWZ((uint32_t)(row * 128 + c16 * 16));
        int sz = (m0 + row < cnt) ? 16 : 0;
        size_t aoff = (size_t)(e * TT + m0 + row) * ID + k0 + c16 * 8;
        cp16(smem_u32(ah + doff), g_ah + aoff, sz);
        cp16(smem_u32(al + doff), g_al + aoff, sz);
        size_t woff = ((size_t)e * HD + n0 + row) * ID + k0 + c16 * 8;
        cp16(smem_u32(wh + doff), g_w2h + woff, 16);
        cp16(smem_u32(wl + doff), g_w2l + woff, 16);
    }
}

__global__ __launch_bounds__(256)
void gemm2_kernel(float* __restrict__ out) {
    extern __shared__ char smem[];
    const int e   = blockIdx.z;
    const int cnt = g_count[e];
    const int m0  = blockIdx.y * 128;
    if (m0 >= cnt) return;
    const int n0  = blockIdx.x * 128;
    const int tid  = threadIdx.x;
    const int wid  = tid >> 5, lane = tid & 31;

    int*   s_tok = (int*)smem;
    float* s_wt  = (float*)(smem + 512);
    if (tid < 128) {
        int m = m0 + tid;
        bool v = (m < cnt);
        s_tok[tid] = v ? g_tok[e * TT + m] : 0;
        s_wt[tid]  = v ? g_wt[e * TT + m] : 0.f;
    }
    __syncthreads();

    const int wm = (wid & 1) * 64;
    const int wn = (wid >> 1) * 32;

    float acc[4][4][4];
#pragma unroll
    for (int mf = 0; mf < 4; mf++)
#pragma unroll
        for (int nf = 0; nf < 4; nf++)
#pragma unroll
            for (int r = 0; r < 4; r++) acc[mf][nf][r] = 0.f;

    g2_load(smem + 1024, e, m0, cnt, n0, 0, tid);
    CP_COMMIT();

    const int NCH = ID / KC;   // 88
    for (int c = 0; c < NCH; c++) {
        if (c + 1 < NCH)
            g2_load(smem + 1024 + ((c + 1) & 1) * STAGE_B, e, m0, cnt, n0, (c + 1) * KC, tid);
        CP_COMMIT();
        CP_WAIT1();
        __syncthreads();

        char* sb = smem + 1024 + (c & 1) * STAGE_B;
        const uint32_t ahb = smem_u32(sb), alb = ahb + 16384;
        const uint32_t whb = ahb + 32768, wlb = ahb + 49152;

#pragma unroll
        for (int kb = 0; kb < 4; kb++) {
            uint32_t ah[4][4], al[4][4];
#pragma unroll
            for (int mf = 0; mf < 4; mf++) {
                uint32_t aa = a_addr(0, wm + mf * 16, kb, lane);
                ldsm4(ah[mf], ahb + aa);
                ldsm4(al[mf], alb + aa);
            }
            uint32_t rwh[2][4], rwl[2][4];
#pragma unroll
            for (int nf2 = 0; nf2 < 2; nf2++) {
                uint32_t ba = b_addr(0, wn + nf2 * 16, kb, lane);
                ldsm4(rwh[nf2], whb + ba);
                ldsm4(rwl[nf2], wlb + ba);
            }
#pragma unroll
            for (int mf = 0; mf < 4; mf++)
#pragma unroll
                for (int nf = 0; nf < 4; nf++) {
                    const int h = nf >> 1, q = (nf & 1) * 2;
                    mma_bf16(acc[mf][nf], ah[mf], &rwh[h][q]);
                    mma_bf16(acc[mf][nf], ah[mf], &rwl[h][q]);
                    mma_bf16(acc[mf][nf], al[mf], &rwh[h][q]);
                }
        }
        __syncthreads();
    }

    // epilogue: atomic weighted combine
#pragma unroll
    for (int mf = 0; mf < 4; mf++) {
#pragma unroll
        for (int rr = 0; rr < 2; rr++) {
            const int lrow = wm + mf * 16 + rr * 8 + (lane >> 2);
            if (m0 + lrow >= cnt) continue;
            const int   tok = s_tok[lrow];
            const float wt  = s_wt[lrow];
            float* op = out + (size_t)tok * HD + n0;
#pragma unroll
            for (int nf = 0; nf < 4; nf++) {
                const int col = wn + nf * 8 + (lane & 3) * 2;
                atomicAdd(op + col,     wt * acc[mf][nf][rr * 2 + 0]);
                atomicAdd(op + col + 1, wt * acc[mf][nf][rr * 2 + 1]);
            }
        }
    }
}

// ---------------- launch ----------------
extern "C" void kernel_launch(void* const* d_in, const int* in_sizes, int n_in,
                              void* d_out, int out_size) {
    const float* x  = (const float*)d_in[0];
    const float* gw = (const float*)d_in[1];
    const float* w1 = (const float*)d_in[2];
    const float* w3 = (const float*)d_in[3];
    const float* w2 = (const float*)d_in[4];
    float* out = (float*)d_out;

    static bool attr_done = false;
    if (!attr_done) {
        cudaFuncSetAttribute(gemm1_kernel, cudaFuncAttributeMaxDynamicSharedMemorySize, SMEM_SZ);
        cudaFuncSetAttribute(gemm2_kernel, cudaFuncAttributeMaxDynamicSharedMemorySize, SMEM_SZ);
        attr_done = true;
    }

    void *cnt_a, *xh_a, *xl_a, *w1h_a, *w1l_a, *w3h_a, *w3l_a, *w2h_a, *w2l_a;
    cudaGetSymbolAddress(&cnt_a, g_count);
    cudaGetSymbolAddress(&xh_a,  g_xh);  cudaGetSymbolAddress(&xl_a,  g_xl);
    cudaGetSymbolAddress(&w1h_a, g_w1h); cudaGetSymbolAddress(&w1l_a, g_w1l);
    cudaGetSymbolAddress(&w3h_a, g_w3h); cudaGetSymbolAddress(&w3l_a, g_w3l);
    cudaGetSymbolAddress(&w2h_a, g_w2h); cudaGetSymbolAddress(&w2l_a, g_w2l);

    cudaMemsetAsync(cnt_a, 0, sizeof(int) * NE, 0);
    cudaMemsetAsync(d_out, 0, sizeof(float) * (size_t)out_size, 0);

    const int nw4 = (int)(WSZ / 4);
    const int nx4 = TT * HD / 4;
    split_kernel<<<(nx4 + 255) / 256, 256>>>(x,  (__nv_bfloat16*)xh_a,  (__nv_bfloat16*)xl_a,  nx4);
    split_kernel<<<(nw4 + 255) / 256, 256>>>(w1, (__nv_bfloat16*)w1h_a, (__nv_bfloat16*)w1l_a, nw4);
    split_kernel<<<(nw4 + 255) / 256, 256>>>(w3, (__nv_bfloat16*)w3h_a, (__nv_bfloat16*)w3l_a, nw4);
    split_kernel<<<(nw4 + 255) / 256, 256>>>(w2, (__nv_bfloat16*)w2h_a, (__nv_bfloat16*)w2l_a, nw4);

    route_kernel<<<TT, 128>>>(x, gw);

    dim3 g1(ID / 64, TT / 128, NE);    // (88, 16, 8)
    gemm1_kernel<<<g1, 256, SMEM_SZ>>>();

    dim3 g2(HD / 128, TT / 128, NE);   // (16, 16, 8)
    gemm2_kernel<<<g2, 256, SMEM_SZ>>>(out);
}

// round 5
// speedup vs baseline: 4.8055x; 1.5345x over previous
#include <cuda_runtime.h>
#include <cuda_fp16.h>
#include <math.h>
#include <stdint.h>

// Problem constants
#define TT   2048      // tokens
#define HD   2048      // hidden
#define ID   5632      // intermediate
#define NE   8         // experts
#define KC   64        // K-chunk (fp16 elems) = 128B row

// ---------------- device scratch ----------------
__device__ int   g_count[NE];
__device__ int   g_tok[NE * TT];
__device__ float g_wt [NE * TT];

#define WSZ (NE * (size_t)ID * HD)
__device__ __half g_w1[WSZ];                    // single fp16 weights
__device__ __half g_w3[WSZ];
__device__ __half g_w2[WSZ];
__device__ __half g_xh[(size_t)TT * HD];        // x hi/lo (exact)
__device__ __half g_xl[(size_t)TT * HD];
__device__ __half g_ah[NE * (size_t)TT * ID];   // act hi/lo (exact)
__device__ __half g_al[NE * (size_t)TT * ID];

// ---------------- helpers ----------------
__device__ __forceinline__ uint32_t smem_u32(const void* p) {
    return (uint32_t)__cvta_generic_to_shared(p);
}
#define SWZ(o) ((o) ^ (((o) >> 3) & 0x70))

__device__ __forceinline__ void cp16(uint32_t dst, const void* src, int sz) {
    asm volatile("cp.async.cg.shared.global [%0], [%1], 16, %2;"
                 :: "r"(dst), "l"(src), "r"(sz) : "memory");
}
#define CP_COMMIT() asm volatile("cp.async.commit_group;" ::: "memory")
#define CP_WAIT1()  asm volatile("cp.async.wait_group 1;" ::: "memory")

__device__ __forceinline__ void ldsm4(uint32_t* r, uint32_t addr) {
    asm volatile("ldmatrix.sync.aligned.m8n8.x4.shared.b16 {%0,%1,%2,%3}, [%4];"
                 : "=r"(r[0]), "=r"(r[1]), "=r"(r[2]), "=r"(r[3]) : "r"(addr));
}
__device__ __forceinline__ void mma_f16(float* d, const uint32_t* a, const uint32_t* b) {
    asm volatile("mma.sync.aligned.m16n8k16.row.col.f32.f16.f16.f32 "
                 "{%0,%1,%2,%3}, {%4,%5,%6,%7}, {%8,%9}, {%0,%1,%2,%3};"
                 : "+f"(d[0]), "+f"(d[1]), "+f"(d[2]), "+f"(d[3])
                 : "r"(a[0]), "r"(a[1]), "r"(a[2]), "r"(a[3]),
                   "r"(b[0]), "r"(b[1]));
}

// A-fragment ldmatrix address (m16 x k16 at (mbase, kb*16) within 128B-row tile)
__device__ __forceinline__ uint32_t a_addr(int mbase, int kb, int lane) {
    int row = mbase + ((lane >> 3) & 1) * 8 + (lane & 7);
    uint32_t off = (uint32_t)(row * 128 + kb * 32 + (lane >> 4) * 16);
    return SWZ(off);
}
// B-fragment ldmatrix address (n16 x k16 at (nbase, kb*16))
__device__ __forceinline__ uint32_t b_addr(int nbase, int kb, int lane) {
    int row = nbase + ((lane >> 4) << 3) + (lane & 7);
    uint32_t off = (uint32_t)(row * 128 + kb * 32 + ((lane >> 3) & 1) * 16);
    return SWZ(off);
}

// ---------------- fp32 -> fp16 convert (weights) ----------------
__global__ void cvt_kernel(const float* __restrict__ src,
                           __half* __restrict__ dst, int n4) {
    int i = blockIdx.x * blockDim.x + threadIdx.x;
    if (i >= n4) return;
    float4 v = ((const float4*)src)[i];
    __half2 p0 = __floats2half2_rn(v.x, v.y);
    __half2 p1 = __floats2half2_rn(v.z, v.w);
    uint2 u;
    u.x = *(uint32_t*)&p0; u.y = *(uint32_t*)&p1;
    ((uint2*)dst)[i] = u;
}

// ---------------- fp32 -> fp16 hi/lo split (x) ----------------
__global__ void split_kernel(const float* __restrict__ src,
                             __half* __restrict__ hi,
                             __half* __restrict__ lo, int n4) {
    int i = blockIdx.x * blockDim.x + threadIdx.x;
    if (i >= n4) return;
    float4 v = ((const float4*)src)[i];
    __half h0 = __float2half_rn(v.x), h1 = __float2half_rn(v.y);
    __half h2 = __float2half_rn(v.z), h3 = __float2half_rn(v.w);
    __half l0 = __float2half_rn(v.x - __half2float(h0));
    __half l1 = __float2half_rn(v.y - __half2float(h1));
    __half l2 = __float2half_rn(v.z - __half2float(h2));
    __half l3 = __float2half_rn(v.w - __half2float(h3));
    __half2 hp0 = __halves2half2(h0, h1), hp1 = __halves2half2(h2, h3);
    __half2 lp0 = __halves2half2(l0, l1), lp1 = __halves2half2(l2, l3);
    uint2 hu, lu;
    hu.x = *(uint32_t*)&hp0; hu.y = *(uint32_t*)&hp1;
    lu.x = *(uint32_t*)&lp0; lu.y = *(uint32_t*)&lp1;
    ((uint2*)hi)[i] = hu;
    ((uint2*)lo)[i] = lu;
}

// ---------------- router ----------------
__global__ void route_kernel(const float* __restrict__ x,
                             const float* __restrict__ gw) {
    const int t   = blockIdx.x;
    const int tid = threadIdx.x;   // 128
    float p[NE];
#pragma unroll
    for (int e = 0; e < NE; e++) p[e] = 0.f;
    const float* xr = x + (size_t)t * HD;
    for (int h = tid; h < HD; h += 128) {
        float xv = xr[h];
#pragma unroll
        for (int e = 0; e < NE; e++) p[e] += xv * gw[e * HD + h];
    }
    __shared__ float sh[NE][128];
#pragma unroll
    for (int e = 0; e < NE; e++) sh[e][tid] = p[e];
    __syncthreads();
    for (int off = 64; off > 0; off >>= 1) {
        if (tid < off) {
#pragma unroll
            for (int e = 0; e < NE; e++) sh[e][tid] += sh[e][tid + off];
        }
        __syncthreads();
    }
    if (tid == 0) {
        float l[NE];
#pragma unroll
        for (int e = 0; e < NE; e++) l[e] = sh[e][0];
        int i0 = 0;
#pragma unroll
        for (int e = 1; e < NE; e++) if (l[e] > l[i0]) i0 = e;
        int i1 = (i0 == 0) ? 1 : 0;
#pragma unroll
        for (int e = 0; e < NE; e++) if (e != i0 && l[e] > l[i1]) i1 = e;
        float d  = expf(l[i1] - l[i0]);
        float w0 = 1.f / (1.f + d);
        float w1 = d / (1.f + d);
        int p0 = atomicAdd(&g_count[i0], 1);
        g_tok[i0 * TT + p0] = t;  g_wt[i0 * TT + p0] = w0;
        int p1 = atomicAdd(&g_count[i1], 1);
        g_tok[i1 * TT + p1] = t;  g_wt[i1 * TT + p1] = w1;
    }
}

// SMEM: [0..512) s_tok, [512..1024) s_wt, stages from 1024, 48KB each
#define STAGE_B 49152
#define SMEM_SZ (1024 + 2 * STAGE_B)

// ---------------- GEMM1: act = silu(x@w1^T) * (x@w3^T) ----------------
// CTA 128(M) x 64(N); 8 warps 4x2 of 32x32.
// stage layout: xh[16K] xl[16K] w1[8K] w3[8K]
__device__ __forceinline__ void g1_load(char* sb, const int* s_tok,
                                        int e, int n0, int k0, int tid) {
    char* xh = sb;           char* xl = sb + 16384;
    char* w1 = sb + 32768;   char* w3 = sb + 40960;
#pragma unroll
    for (int it = 0; it < 4; it++) {
        int i = tid + it * 256;
        int row = i >> 3, c16 = i & 7;
        int tok = s_tok[row];
        uint32_t doff = SWZ((uint32_t)(row * 128 + c16 * 16));
        size_t goff = (size_t)(tok < 0 ? 0 : tok) * HD + k0 + c16 * 8;
        int sz = (tok < 0) ? 0 : 16;
        cp16(smem_u32(xh + doff), g_xh + goff, sz);
        cp16(smem_u32(xl + doff), g_xl + goff, sz);
    }
#pragma unroll
    for (int it = 0; it < 2; it++) {
        int i = tid + it * 256;
        int row = i >> 3, c16 = i & 7;
        uint32_t doff = SWZ((uint32_t)(row * 128 + c16 * 16));
        size_t goff = ((size_t)e * ID + n0 + row) * HD + k0 + c16 * 8;
        cp16(smem_u32(w1 + doff), g_w1 + goff, 16);
        cp16(smem_u32(w3 + doff), g_w3 + goff, 16);
    }
}

__global__ __launch_bounds__(256)
void gemm1_kernel() {
    extern __shared__ char smem[];
    const int e   = blockIdx.z;
    const int cnt = g_count[e];
    const int m0  = blockIdx.y * 128;
    if (m0 >= cnt) return;
    const int n0  = blockIdx.x * 64;
    const int tid  = threadIdx.x;
    const int wid  = tid >> 5, lane = tid & 31;

    int* s_tok = (int*)smem;
    if (tid < 128) {
        int m = m0 + tid;
        s_tok[tid] = (m < cnt) ? g_tok[e * TT + m] : -1;
    }
    __syncthreads();

    const int wm = (wid & 3) * 32;   // warp M offset
    const int wn = (wid >> 2) * 32;  // warp N offset

    float accg[2][4][4], accu[2][4][4];
#pragma unroll
    for (int mf = 0; mf < 2; mf++)
#pragma unroll
        for (int nf = 0; nf < 4; nf++)
#pragma unroll
            for (int r = 0; r < 4; r++) { accg[mf][nf][r] = 0.f; accu[mf][nf][r] = 0.f; }

    g1_load(smem + 1024, s_tok, e, n0, 0, tid);
    CP_COMMIT();

    const int NCH = HD / KC;   // 32
    for (int c = 0; c < NCH; c++) {
        if (c + 1 < NCH)
            g1_load(smem + 1024 + ((c + 1) & 1) * STAGE_B, s_tok, e, n0, (c + 1) * KC, tid);
        CP_COMMIT();
        CP_WAIT1();
        __syncthreads();

        char* sb = smem + 1024 + (c & 1) * STAGE_B;
        const uint32_t xh = smem_u32(sb), xl = xh + 16384;
        const uint32_t b1 = xh + 32768,   b3 = xh + 40960;

#pragma unroll
        for (int kb = 0; kb < 4; kb++) {
            uint32_t ah[2][4], al[2][4];
#pragma unroll
            for (int mf = 0; mf < 2; mf++) {
                uint32_t aa = a_addr(wm + mf * 16, kb, lane);
                ldsm4(ah[mf], xh + aa);
                ldsm4(al[mf], xl + aa);
            }
            uint32_t r1[2][4], r3[2][4];
#pragma unroll
            for (int nf2 = 0; nf2 < 2; nf2++) {
                uint32_t ba = b_addr(wn + nf2 * 16, kb, lane);
                ldsm4(r1[nf2], b1 + ba);
                ldsm4(r3[nf2], b3 + ba);
            }
#pragma unroll
            for (int mf = 0; mf < 2; mf++)
#pragma unroll
                for (int nf = 0; nf < 4; nf++) {
                    const int h = nf >> 1, q = (nf & 1) * 2;
                    mma_f16(accg[mf][nf], ah[mf], &r1[h][q]);
                    mma_f16(accg[mf][nf], al[mf], &r1[h][q]);
                    mma_f16(accu[mf][nf], ah[mf], &r3[h][q]);
                    mma_f16(accu[mf][nf], al[mf], &r3[h][q]);
                }
        }
        __syncthreads();
    }

    // epilogue: silu(g)*u -> fp16 hi/lo act
#pragma unroll
    for (int mf = 0; mf < 2; mf++) {
#pragma unroll
        for (int rr = 0; rr < 2; rr++) {
            const int slot = m0 + wm + mf * 16 + rr * 8 + (lane >> 2);
            if (slot >= cnt) continue;
            const size_t base = (size_t)(e * TT + slot) * ID + n0;
#pragma unroll
            for (int nf = 0; nf < 4; nf++) {
                float g0 = accg[mf][nf][rr * 2 + 0], g1 = accg[mf][nf][rr * 2 + 1];
                float u0 = accu[mf][nf][rr * 2 + 0], u1 = accu[mf][nf][rr * 2 + 1];
                float a0 = u0 * g0 / (1.f + expf(-g0));
                float a1 = u1 * g1 / (1.f + expf(-g1));
                __half h0 = __float2half_rn(a0), h1 = __float2half_rn(a1);
                __half l0 = __float2half_rn(a0 - __half2float(h0));
                __half l1 = __float2half_rn(a1 - __half2float(h1));
                const int col = wn + nf * 8 + (lane & 3) * 2;
                *(__half2*)(g_ah + base + col) = __halves2half2(h0, h1);
                *(__half2*)(g_al + base + col) = __halves2half2(l0, l1);
            }
        }
    }
}

// ---------------- GEMM2: out[tok] += wt * (act @ w2^T) ----------------
// CTA 128(M) x 128(N); 8 warps 2x4 of 64x32.
// stage layout: ah[16K] al[16K] w2[16K]
__device__ __forceinline__ void g2_load(char* sb, int e, int m0, int cnt,
                                        int n0, int k0, int tid) {
    char* ah = sb;           char* al = sb + 16384;
    char* wh = sb + 32768;
#pragma unroll
    for (int it = 0; it < 4; it++) {
        int i = tid + it * 256;
        int row = i >> 3, c16 = i & 7;
        uint32_t doff = SWZ((uint32_t)(row * 128 + c16 * 16));
        int sz = (m0 + row < cnt) ? 16 : 0;
        size_t aoff = (size_t)(e * TT + m0 + row) * ID + k0 + c16 * 8;
        cp16(smem_u32(ah + doff), g_ah + aoff, sz);
        cp16(smem_u32(al + doff), g_al + aoff, sz);
        size_t woff = ((size_t)e * HD + n0 + row) * ID + k0 + c16 * 8;
        cp16(smem_u32(wh + doff), g_w2 + woff, 16);
    }
}

__global__ __launch_bounds__(256)
void gemm2_kernel(float* __restrict__ out) {
    extern __shared__ char smem[];
    const int e   = blockIdx.z;
    const int cnt = g_count[e];
    const int m0  = blockIdx.y * 128;
    if (m0 >= cnt) return;
    const int n0  = blockIdx.x * 128;
    const int tid  = threadIdx.x;
    const int wid  = tid >> 5, lane = tid & 31;

    int*   s_tok = (int*)smem;
    float* s_wt  = (float*)(smem + 512);
    if (tid < 128) {
        int m = m0 + tid;
        bool v = (m < cnt);
        s_tok[tid] = v ? g_tok[e * TT + m] : 0;
        s_wt[tid]  = v ? g_wt[e * TT + m] : 0.f;
    }
    __syncthreads();

    const int wm = (wid & 1) * 64;
    const int wn = (wid >> 1) * 32;

    float acc[4][4][4];
#pragma unroll
    for (int mf = 0; mf < 4; mf++)
#pragma unroll
        for (int nf = 0; nf < 4; nf++)
#pragma unroll
            for (int r = 0; r < 4; r++) acc[mf][nf][r] = 0.f;

    g2_load(smem + 1024, e, m0, cnt, n0, 0, tid);
    CP_COMMIT();

    const int NCH = ID / KC;   // 88
    for (int c = 0; c < NCH; c++) {
        if (c + 1 < NCH)
            g2_load(smem + 1024 + ((c + 1) & 1) * STAGE_B, e, m0, cnt, n0, (c + 1) * KC, tid);
        CP_COMMIT();
        CP_WAIT1();
        __syncthreads();

        char* sb = smem + 1024 + (c & 1) * STAGE_B;
        const uint32_t ahb = smem_u32(sb), alb = ahb + 16384;
        const uint32_t whb = ahb + 32768;

#pragma unroll
        for (int kb = 0; kb < 4; kb++) {
            uint32_t ah[4][4], al[4][4];
#pragma unroll
            for (int mf = 0; mf < 4; mf++) {
                uint32_t aa = a_addr(wm + mf * 16, kb, lane);
                ldsm4(ah[mf], ahb + aa);
                ldsm4(al[mf], alb + aa);
            }
            uint32_t rw[2][4];
#pragma unroll
            for (int nf2 = 0; nf2 < 2; nf2++) {
                uint32_t ba = b_addr(wn + nf2 * 16, kb, lane);
                ldsm4(rw[nf2], whb + ba);
            }
#pragma unroll
            for (int mf = 0; mf < 4; mf++)
#pragma unroll
                for (int nf = 0; nf < 4; nf++) {
                    const int h = nf >> 1, q = (nf & 1) * 2;
                    mma_f16(acc[mf][nf], ah[mf], &rw[h][q]);
                    mma_f16(acc[mf][nf], al[mf], &rw[h][q]);
                }
        }
        __syncthreads();
    }

    // epilogue: atomic weighted combine
#pragma unroll
    for (int mf = 0; mf < 4; mf++) {
#pragma unroll
        for (int rr = 0; rr < 2; rr++) {
            const int lrow = wm + mf * 16 + rr * 8 + (lane >> 2);
            if (m0 + lrow >= cnt) continue;
            const int   tok = s_tok[lrow];
            const float wt  = s_wt[lrow];
            float* op = out + (size_t)tok * HD + n0;
#pragma unroll
            for (int nf = 0; nf < 4; nf++) {
                const int col = wn + nf * 8 + (lane & 3) * 2;
                atomicAdd(op + col,     wt * acc[mf][nf][rr * 2 + 0]);
                atomicAdd(op + col + 1, wt * acc[mf][nf][rr * 2 + 1]);
            }
        }
    }
}

// ---------------- launch ----------------
extern "C" void kernel_launch(void* const* d_in, const int* in_sizes, int n_in,
                              void* d_out, int out_size) {
    const float* x  = (const float*)d_in[0];
    const float* gw = (const float*)d_in[1];
    const float* w1 = (const float*)d_in[2];
    const float* w3 = (const float*)d_in[3];
    const float* w2 = (const float*)d_in[4];
    float* out = (float*)d_out;

    static bool attr_done = false;
    if (!attr_done) {
        cudaFuncSetAttribute(gemm1_kernel, cudaFuncAttributeMaxDynamicSharedMemorySize, SMEM_SZ);
        cudaFuncSetAttribute(gemm2_kernel, cudaFuncAttributeMaxDynamicSharedMemorySize, SMEM_SZ);
        attr_done = true;
    }

    void *cnt_a, *xh_a, *xl_a, *w1_a, *w3_a, *w2_a;
    cudaGetSymbolAddress(&cnt_a, g_count);
    cudaGetSymbolAddress(&xh_a, g_xh);  cudaGetSymbolAddress(&xl_a, g_xl);
    cudaGetSymbolAddress(&w1_a, g_w1);  cudaGetSymbolAddress(&w3_a, g_w3);
    cudaGetSymbolAddress(&w2_a, g_w2);

    cudaMemsetAsync(cnt_a, 0, sizeof(int) * NE, 0);
    cudaMemsetAsync(d_out, 0, sizeof(float) * (size_t)out_size, 0);

    const int nw4 = (int)(WSZ / 4);
    const int nx4 = TT * HD / 4;
    split_kernel<<<(nx4 + 255) / 256, 256>>>(x, (__half*)xh_a, (__half*)xl_a, nx4);
    cvt_kernel<<<(nw4 + 255) / 256, 256>>>(w1, (__half*)w1_a, nw4);
    cvt_kernel<<<(nw4 + 255) / 256, 256>>>(w3, (__half*)w3_a, nw4);
    cvt_kernel<<<(nw4 + 255) / 256, 256>>>(w2, (__half*)w2_a, nw4);

    route_kernel<<<TT, 128>>>(x, gw);

    dim3 g1(ID / 64, TT / 128, NE);    // (88, 16, 8)
    gemm1_kernel<<<g1, 256, SMEM_SZ>>>();

    dim3 g2(HD / 128, TT / 128, NE);   // (16, 16, 8)
    gemm2_kernel<<<g2, 256, SMEM_SZ>>>(out);
}

// round 6
// speedup vs baseline: 7.3600x; 1.5316x over previous
#include <cuda_runtime.h>
#include <cuda_fp16.h>
#include <math.h>
#include <stdint.h>

// Problem constants
#define TT   2048      // tokens
#define HD   2048      // hidden
#define ID   5632      // intermediate
#define NE   8         // experts
#define KC   64        // K-chunk (fp16 elems) = 128B row

// ---------------- device scratch ----------------
__device__ int   g_count[NE];
__device__ int   g_tok[NE * TT];
__device__ float g_wt [NE * TT];

#define WSZ (NE * (size_t)ID * HD)
__device__ __half g_w1[WSZ];
__device__ __half g_w3[WSZ];
__device__ __half g_w2[WSZ];
__device__ __half g_x  [(size_t)TT * HD];
__device__ __half g_act[NE * (size_t)TT * ID];

// ---------------- helpers ----------------
__device__ __forceinline__ uint32_t smem_u32(const void* p) {
    return (uint32_t)__cvta_generic_to_shared(p);
}
#define SWZ(o) ((o) ^ (((o) >> 3) & 0x70))

__device__ __forceinline__ void cp16(uint32_t dst, const void* src, int sz) {
    asm volatile("cp.async.cg.shared.global [%0], [%1], 16, %2;"
                 :: "r"(dst), "l"(src), "r"(sz) : "memory");
}
#define CP_COMMIT() asm volatile("cp.async.commit_group;" ::: "memory")
#define CP_WAIT1()  asm volatile("cp.async.wait_group 1;" ::: "memory")

__device__ __forceinline__ void ldsm4(uint32_t* r, uint32_t addr) {
    asm volatile("ldmatrix.sync.aligned.m8n8.x4.shared.b16 {%0,%1,%2,%3}, [%4];"
                 : "=r"(r[0]), "=r"(r[1]), "=r"(r[2]), "=r"(r[3]) : "r"(addr));
}
__device__ __forceinline__ void mma_f16(float* d, const uint32_t* a, const uint32_t* b) {
    asm volatile("mma.sync.aligned.m16n8k16.row.col.f32.f16.f16.f32 "
                 "{%0,%1,%2,%3}, {%4,%5,%6,%7}, {%8,%9}, {%0,%1,%2,%3};"
                 : "+f"(d[0]), "+f"(d[1]), "+f"(d[2]), "+f"(d[3])
                 : "r"(a[0]), "r"(a[1]), "r"(a[2]), "r"(a[3]),
                   "r"(b[0]), "r"(b[1]));
}

// A-fragment ldmatrix address (m16 x k16 at (mbase, kb*16) within 128B-row tile)
__device__ __forceinline__ uint32_t a_addr(int mbase, int kb, int lane) {
    int row = mbase + ((lane >> 3) & 1) * 8 + (lane & 7);
    uint32_t off = (uint32_t)(row * 128 + kb * 32 + (lane >> 4) * 16);
    return SWZ(off);
}
// B-fragment ldmatrix address (n16 x k16 at (nbase, kb*16))
__device__ __forceinline__ uint32_t b_addr(int nbase, int kb, int lane) {
    int row = nbase + ((lane >> 4) << 3) + (lane & 7);
    uint32_t off = (uint32_t)(row * 128 + kb * 32 + ((lane >> 3) & 1) * 16);
    return SWZ(off);
}

// ---------------- fp32 -> fp16 convert ----------------
__global__ void cvt_kernel(const float* __restrict__ src,
                           __half* __restrict__ dst, int n4) {
    int i = blockIdx.x * blockDim.x + threadIdx.x;
    if (i >= n4) return;
    float4 v = ((const float4*)src)[i];
    __half2 p0 = __floats2half2_rn(v.x, v.y);
    __half2 p1 = __floats2half2_rn(v.z, v.w);
    uint2 u;
    u.x = *(uint32_t*)&p0; u.y = *(uint32_t*)&p1;
    ((uint2*)dst)[i] = u;
}

// ---------------- router ----------------
__global__ void route_kernel(const float* __restrict__ x,
                             const float* __restrict__ gw) {
    const int t   = blockIdx.x;
    const int tid = threadIdx.x;   // 128
    float p[NE];
#pragma unroll
    for (int e = 0; e < NE; e++) p[e] = 0.f;
    const float* xr = x + (size_t)t * HD;
    for (int h = tid; h < HD; h += 128) {
        float xv = xr[h];
#pragma unroll
        for (int e = 0; e < NE; e++) p[e] += xv * gw[e * HD + h];
    }
    __shared__ float sh[NE][128];
#pragma unroll
    for (int e = 0; e < NE; e++) sh[e][tid] = p[e];
    __syncthreads();
    for (int off = 64; off > 0; off >>= 1) {
        if (tid < off) {
#pragma unroll
            for (int e = 0; e < NE; e++) sh[e][tid] += sh[e][tid + off];
        }
        __syncthreads();
    }
    if (tid == 0) {
        float l[NE];
#pragma unroll
        for (int e = 0; e < NE; e++) l[e] = sh[e][0];
        int i0 = 0;
#pragma unroll
        for (int e = 1; e < NE; e++) if (l[e] > l[i0]) i0 = e;
        int i1 = (i0 == 0) ? 1 : 0;
#pragma unroll
        for (int e = 0; e < NE; e++) if (e != i0 && l[e] > l[i1]) i1 = e;
        float d  = expf(l[i1] - l[i0]);
        float w0 = 1.f / (1.f + d);
        float w1 = d / (1.f + d);
        int p0 = atomicAdd(&g_count[i0], 1);
        g_tok[i0 * TT + p0] = t;  g_wt[i0 * TT + p0] = w0;
        int p1 = atomicAdd(&g_count[i1], 1);
        g_tok[i1 * TT + p1] = t;  g_wt[i1 * TT + p1] = w1;
    }
}

// SMEM: [0..512) s_tok, [512..1024) s_wt, 3 stages from 1024, 32KB each
#define STAGE_B 32768
#define NSTAGE  3
#define SMEM_SZ (1024 + NSTAGE * STAGE_B)

// ---------------- GEMM1: act = silu(x@w1^T) * (x@w3^T) ----------------
// CTA 128(M) x 64(N); 8 warps 4x2 of 32x32.
// stage layout: x[16K] w1[8K] w3[8K]
__device__ __forceinline__ void g1_load(char* sb, const int* s_tok,
                                        int e, int n0, int k0, int tid) {
    char* xs = sb;
    char* w1 = sb + 16384;
    char* w3 = sb + 24576;
#pragma unroll
    for (int it = 0; it < 4; it++) {
        int i = tid + it * 256;
        int row = i >> 3, c16 = i & 7;
        int tok = s_tok[row];
        uint32_t doff = SWZ((uint32_t)(row * 128 + c16 * 16));
        size_t goff = (size_t)(tok < 0 ? 0 : tok) * HD + k0 + c16 * 8;
        cp16(smem_u32(xs + doff), g_x + goff, (tok < 0) ? 0 : 16);
    }
#pragma unroll
    for (int it = 0; it < 2; it++) {
        int i = tid + it * 256;
        int row = i >> 3, c16 = i & 7;
        uint32_t doff = SWZ((uint32_t)(row * 128 + c16 * 16));
        size_t goff = ((size_t)e * ID + n0 + row) * HD + k0 + c16 * 8;
        cp16(smem_u32(w1 + doff), g_w1 + goff, 16);
        cp16(smem_u32(w3 + doff), g_w3 + goff, 16);
    }
}

__global__ __launch_bounds__(256)
void gemm1_kernel() {
    extern __shared__ char smem[];
    const int e   = blockIdx.z;
    const int cnt = g_count[e];
    const int m0  = blockIdx.y * 128;
    if (m0 >= cnt) return;
    const int n0  = blockIdx.x * 64;
    const int tid  = threadIdx.x;
    const int wid  = tid >> 5, lane = tid & 31;

    int* s_tok = (int*)smem;
    if (tid < 128) {
        int m = m0 + tid;
        s_tok[tid] = (m < cnt) ? g_tok[e * TT + m] : -1;
    }
    __syncthreads();

    const int wm = (wid & 3) * 32;
    const int wn = (wid >> 2) * 32;

    float accg[2][4][4], accu[2][4][4];
#pragma unroll
    for (int mf = 0; mf < 2; mf++)
#pragma unroll
        for (int nf = 0; nf < 4; nf++)
#pragma unroll
            for (int r = 0; r < 4; r++) { accg[mf][nf][r] = 0.f; accu[mf][nf][r] = 0.f; }

    g1_load(smem + 1024, s_tok, e, n0, 0, tid);
    CP_COMMIT();
    g1_load(smem + 1024 + STAGE_B, s_tok, e, n0, KC, tid);
    CP_COMMIT();

    const int NCH = HD / KC;   // 32
    for (int c = 0; c < NCH; c++) {
        CP_WAIT1();
        __syncthreads();

        char* sb = smem + 1024 + (c % NSTAGE) * STAGE_B;
        const uint32_t xs = smem_u32(sb);
        const uint32_t b1 = xs + 16384, b3 = xs + 24576;

#pragma unroll
        for (int kb = 0; kb < 4; kb++) {
            uint32_t af[2][4];
#pragma unroll
            for (int mf = 0; mf < 2; mf++)
                ldsm4(af[mf], xs + a_addr(wm + mf * 16, kb, lane));
            uint32_t r1[2][4], r3[2][4];
#pragma unroll
            for (int nf2 = 0; nf2 < 2; nf2++) {
                uint32_t ba = b_addr(wn + nf2 * 16, kb, lane);
                ldsm4(r1[nf2], b1 + ba);
                ldsm4(r3[nf2], b3 + ba);
            }
#pragma unroll
            for (int mf = 0; mf < 2; mf++)
#pragma unroll
                for (int nf = 0; nf < 4; nf++) {
                    const int h = nf >> 1, q = (nf & 1) * 2;
                    mma_f16(accg[mf][nf], af[mf], &r1[h][q]);
                    mma_f16(accu[mf][nf], af[mf], &r3[h][q]);
                }
        }
        __syncthreads();
        if (c + 2 < NCH) {
            g1_load(smem + 1024 + ((c + 2) % NSTAGE) * STAGE_B, s_tok, e, n0, (c + 2) * KC, tid);
            CP_COMMIT();
        } else {
            CP_COMMIT();   // keep group count in step for CP_WAIT1
        }
    }

    // epilogue: silu(g)*u -> fp16 act
#pragma unroll
    for (int mf = 0; mf < 2; mf++) {
#pragma unroll
        for (int rr = 0; rr < 2; rr++) {
            const int slot = m0 + wm + mf * 16 + rr * 8 + (lane >> 2);
            if (slot >= cnt) continue;
            const size_t base = (size_t)(e * TT + slot) * ID + n0;
#pragma unroll
            for (int nf = 0; nf < 4; nf++) {
                float g0 = accg[mf][nf][rr * 2 + 0], g1 = accg[mf][nf][rr * 2 + 1];
                float u0 = accu[mf][nf][rr * 2 + 0], u1 = accu[mf][nf][rr * 2 + 1];
                float a0 = u0 * g0 / (1.f + expf(-g0));
                float a1 = u1 * g1 / (1.f + expf(-g1));
                const int col = wn + nf * 8 + (lane & 3) * 2;
                *(__half2*)(g_act + base + col) = __floats2half2_rn(a0, a1);
            }
        }
    }
}

// ---------------- GEMM2: out[tok] += wt * (act @ w2^T) ----------------
// CTA 128(M) x 128(N); 8 warps 2x4 of 64x32.
// stage layout: a[16K] w2[16K]
__device__ __forceinline__ void g2_load(char* sb, int e, int m0, int cnt,
                                        int n0, int k0, int tid) {
    char* as = sb;
    char* ws = sb + 16384;
#pragma unroll
    for (int it = 0; it < 4; it++) {
        int i = tid + it * 256;
        int row = i >> 3, c16 = i & 7;
        uint32_t doff = SWZ((uint32_t)(row * 128 + c16 * 16));
        size_t aoff = (size_t)(e * TT + m0 + row) * ID + k0 + c16 * 8;
        cp16(smem_u32(as + doff), g_act + aoff, (m0 + row < cnt) ? 16 : 0);
        size_t woff = ((size_t)e * HD + n0 + row) * ID + k0 + c16 * 8;
        cp16(smem_u32(ws + doff), g_w2 + woff, 16);
    }
}

__global__ __launch_bounds__(256)
void gemm2_kernel(float* __restrict__ out) {
    extern __shared__ char smem[];
    const int e   = blockIdx.z;
    const int cnt = g_count[e];
    const int m0  = blockIdx.y * 128;
    if (m0 >= cnt) return;
    const int n0  = blockIdx.x * 128;
    const int tid  = threadIdx.x;
    const int wid  = tid >> 5, lane = tid & 31;

    int*   s_tok = (int*)smem;
    float* s_wt  = (float*)(smem + 512);
    if (tid < 128) {
        int m = m0 + tid;
        bool v = (m < cnt);
        s_tok[tid] = v ? g_tok[e * TT + m] : 0;
        s_wt[tid]  = v ? g_wt[e * TT + m] : 0.f;
    }
    __syncthreads();

    const int wm = (wid & 1) * 64;
    const int wn = (wid >> 1) * 32;

    float acc[4][4][4];
#pragma unroll
    for (int mf = 0; mf < 4; mf++)
#pragma unroll
        for (int nf = 0; nf < 4; nf++)
#pragma unroll
            for (int r = 0; r < 4; r++) acc[mf][nf][r] = 0.f;

    g2_load(smem + 1024, e, m0, cnt, n0, 0, tid);
    CP_COMMIT();
    g2_load(smem + 1024 + STAGE_B, e, m0, cnt, n0, KC, tid);
    CP_COMMIT();

    const int NCH = ID / KC;   // 88
    for (int c = 0; c < NCH; c++) {
        CP_WAIT1();
        __syncthreads();

        char* sb = smem + 1024 + (c % NSTAGE) * STAGE_B;
        const uint32_t ab = smem_u32(sb);
        const uint32_t wb = ab + 16384;

#pragma unroll
        for (int kb = 0; kb < 4; kb++) {
            uint32_t af[4][4];
#pragma unroll
            for (int mf = 0; mf < 4; mf++)
                ldsm4(af[mf], ab + a_addr(wm + mf * 16, kb, lane));
            uint32_t rw[2][4];
#pragma unroll
            for (int nf2 = 0; nf2 < 2; nf2++)
                ldsm4(rw[nf2], wb + b_addr(wn + nf2 * 16, kb, lane));
#pragma unroll
            for (int mf = 0; mf < 4; mf++)
#pragma unroll
                for (int nf = 0; nf < 4; nf++) {
                    const int h = nf >> 1, q = (nf & 1) * 2;
                    mma_f16(acc[mf][nf], af[mf], &rw[h][q]);
                }
        }
        __syncthreads();
        if (c + 2 < NCH) {
            g2_load(smem + 1024 + ((c + 2) % NSTAGE) * STAGE_B, e, m0, cnt, n0, (c + 2) * KC, tid);
            CP_COMMIT();
        } else {
            CP_COMMIT();
        }
    }

    // epilogue: atomic weighted combine
#pragma unroll
    for (int mf = 0; mf < 4; mf++) {
#pragma unroll
        for (int rr = 0; rr < 2; rr++) {
            const int lrow = wm + mf * 16 + rr * 8 + (lane >> 2);
            if (m0 + lrow >= cnt) continue;
            const int   tok = s_tok[lrow];
            const float wt  = s_wt[lrow];
            float* op = out + (size_t)tok * HD + n0;
#pragma unroll
            for (int nf = 0; nf < 4; nf++) {
                const int col = wn + nf * 8 + (lane & 3) * 2;
                atomicAdd(op + col,     wt * acc[mf][nf][rr * 2 + 0]);
                atomicAdd(op + col + 1, wt * acc[mf][nf][rr * 2 + 1]);
            }
        }
    }
}

// ---------------- launch ----------------
extern "C" void kernel_launch(void* const* d_in, const int* in_sizes, int n_in,
                              void* d_out, int out_size) {
    const float* x  = (const float*)d_in[0];
    const float* gw = (const float*)d_in[1];
    const float* w1 = (const float*)d_in[2];
    const float* w3 = (const float*)d_in[3];
    const float* w2 = (const float*)d_in[4];
    float* out = (float*)d_out;

    static bool attr_done = false;
    if (!attr_done) {
        cudaFuncSetAttribute(gemm1_kernel, cudaFuncAttributeMaxDynamicSharedMemorySize, SMEM_SZ);
        cudaFuncSetAttribute(gemm2_kernel, cudaFuncAttributeMaxDynamicSharedMemorySize, SMEM_SZ);
        attr_done = true;
    }

    void *cnt_a, *x_a, *w1_a, *w3_a, *w2_a;
    cudaGetSymbolAddress(&cnt_a, g_count);
    cudaGetSymbolAddress(&x_a,  g_x);
    cudaGetSymbolAddress(&w1_a, g_w1);
    cudaGetSymbolAddress(&w3_a, g_w3);
    cudaGetSymbolAddress(&w2_a, g_w2);

    cudaMemsetAsync(cnt_a, 0, sizeof(int) * NE, 0);
    cudaMemsetAsync(d_out, 0, sizeof(float) * (size_t)out_size, 0);

    const int nw4 = (int)(WSZ / 4);
    const int nx4 = TT * HD / 4;
    cvt_kernel<<<(nx4 + 255) / 256, 256>>>(x,  (__half*)x_a,  nx4);
    cvt_kernel<<<(nw4 + 255) / 256, 256>>>(w1, (__half*)w1_a, nw4);
    cvt_kernel<<<(nw4 + 255) / 256, 256>>>(w3, (__half*)w3_a, nw4);
    cvt_kernel<<<(nw4 + 255) / 256, 256>>>(w2, (__half*)w2_a, nw4);

    route_kernel<<<TT, 128>>>(x, gw);

    dim3 g1(ID / 64, TT / 128, NE);    // (88, 16, 8)
    gemm1_kernel<<<g1, 256, SMEM_SZ>>>();

    dim3 g2(HD / 128, TT / 128, NE);   // (16, 16, 8)
    gemm2_kernel<<<g2, 256, SMEM_SZ>>>(out);
}

// round 7
// speedup vs baseline: 7.7335x; 1.0507x over previous
#include <cuda_runtime.h>
#include <cuda_fp16.h>
#include <math.h>
#include <stdint.h>

// Problem constants
#define TT   2048      // tokens
#define HD   2048      // hidden
#define ID   5632      // intermediate
#define NE   8         // experts
#define KC   64        // K-chunk (fp16 elems) = 128B row

// ---------------- device scratch ----------------
__device__ int   g_count[NE];
__device__ int   g_tok[NE * TT];
__device__ float g_wt [NE * TT];

#define WSZ (NE * (size_t)ID * HD)
__device__ __half g_w1[WSZ];
__device__ __half g_w3[WSZ];
__device__ __half g_w2[WSZ];
__device__ __half g_x  [(size_t)TT * HD];
__device__ __half g_act[NE * (size_t)TT * ID];

// ---------------- helpers ----------------
__device__ __forceinline__ uint32_t smem_u32(const void* p) {
    return (uint32_t)__cvta_generic_to_shared(p);
}
#define SWZ(o) ((o) ^ (((o) >> 3) & 0x70))

__device__ __forceinline__ void cp16(uint32_t dst, const void* src, int sz) {
    asm volatile("cp.async.cg.shared.global [%0], [%1], 16, %2;"
                 :: "r"(dst), "l"(src), "r"(sz) : "memory");
}
#define CP_COMMIT() asm volatile("cp.async.commit_group;" ::: "memory")
#define CP_WAIT1()  asm volatile("cp.async.wait_group 1;" ::: "memory")

__device__ __forceinline__ void ldsm4(uint32_t* r, uint32_t addr) {
    asm volatile("ldmatrix.sync.aligned.m8n8.x4.shared.b16 {%0,%1,%2,%3}, [%4];"
                 : "=r"(r[0]), "=r"(r[1]), "=r"(r[2]), "=r"(r[3]) : "r"(addr));
}
__device__ __forceinline__ void mma_f16(float* d, const uint32_t* a, const uint32_t* b) {
    asm volatile("mma.sync.aligned.m16n8k16.row.col.f32.f16.f16.f32 "
                 "{%0,%1,%2,%3}, {%4,%5,%6,%7}, {%8,%9}, {%0,%1,%2,%3};"
                 : "+f"(d[0]), "+f"(d[1]), "+f"(d[2]), "+f"(d[3])
                 : "r"(a[0]), "r"(a[1]), "r"(a[2]), "r"(a[3]),
                   "r"(b[0]), "r"(b[1]));
}

// A-fragment ldmatrix address (m16 x k16 at (mbase, kb*16) within 128B-row tile)
__device__ __forceinline__ uint32_t a_addr(int mbase, int kb, int lane) {
    int row = mbase + ((lane >> 3) & 1) * 8 + (lane & 7);
    uint32_t off = (uint32_t)(row * 128 + kb * 32 + (lane >> 4) * 16);
    return SWZ(off);
}
// B-fragment ldmatrix address (n16 x k16 at (nbase, kb*16))
__device__ __forceinline__ uint32_t b_addr(int nbase, int kb, int lane) {
    int row = nbase + ((lane >> 4) << 3) + (lane & 7);
    uint32_t off = (uint32_t)(row * 128 + kb * 32 + ((lane >> 3) & 1) * 16);
    return SWZ(off);
}

// ---------------- fp32 -> fp16 convert ----------------
__global__ void cvt_kernel(const float* __restrict__ src,
                           __half* __restrict__ dst, int n4) {
    int i = blockIdx.x * blockDim.x + threadIdx.x;
    if (i >= n4) return;
    float4 v = ((const float4*)src)[i];
    __half2 p0 = __floats2half2_rn(v.x, v.y);
    __half2 p1 = __floats2half2_rn(v.z, v.w);
    uint2 u;
    u.x = *(uint32_t*)&p0; u.y = *(uint32_t*)&p1;
    ((uint2*)dst)[i] = u;
}

// ---------------- router ----------------
__global__ void route_kernel(const float* __restrict__ x,
                             const float* __restrict__ gw) {
    const int t   = blockIdx.x;
    const int tid = threadIdx.x;   // 128
    float p[NE];
#pragma unroll
    for (int e = 0; e < NE; e++) p[e] = 0.f;
    const float* xr = x + (size_t)t * HD;
    for (int h = tid; h < HD; h += 128) {
        float xv = xr[h];
#pragma unroll
        for (int e = 0; e < NE; e++) p[e] += xv * gw[e * HD + h];
    }
    __shared__ float sh[NE][128];
#pragma unroll
    for (int e = 0; e < NE; e++) sh[e][tid] = p[e];
    __syncthreads();
    for (int off = 64; off > 0; off >>= 1) {
        if (tid < off) {
#pragma unroll
            for (int e = 0; e < NE; e++) sh[e][tid] += sh[e][tid + off];
        }
        __syncthreads();
    }
    if (tid == 0) {
        float l[NE];
#pragma unroll
        for (int e = 0; e < NE; e++) l[e] = sh[e][0];
        int i0 = 0;
#pragma unroll
        for (int e = 1; e < NE; e++) if (l[e] > l[i0]) i0 = e;
        int i1 = (i0 == 0) ? 1 : 0;
#pragma unroll
        for (int e = 0; e < NE; e++) if (e != i0 && l[e] > l[i1]) i1 = e;
        float d  = expf(l[i1] - l[i0]);
        float w0 = 1.f / (1.f + d);
        float w1 = d / (1.f + d);
        int p0 = atomicAdd(&g_count[i0], 1);
        g_tok[i0 * TT + p0] = t;  g_wt[i0 * TT + p0] = w0;
        int p1 = atomicAdd(&g_count[i1], 1);
        g_tok[i1 * TT + p1] = t;  g_wt[i1 * TT + p1] = w1;
    }
}

// SMEM: [0..512) s_tok, [512..1024) s_wt, 3 stages from 1024, 32KB each
#define STAGE_B 32768
#define NSTAGE  3
#define SMEM_SZ (1024 + NSTAGE * STAGE_B)

// ---------------- GEMM1: act = silu(x@w1^T) * (x@w3^T) ----------------
// CTA 128(M) x 64(N); 8 warps 4x2 of 32x32.
// stage layout: x[16K] w1[8K] w3[8K]
__device__ __forceinline__ void g1_load(char* sb, const int* s_tok,
                                        int e, int n0, int k0, int tid) {
    char* xs = sb;
    char* w1 = sb + 16384;
    char* w3 = sb + 24576;
#pragma unroll
    for (int it = 0; it < 4; it++) {
        int i = tid + it * 256;
        int row = i >> 3, c16 = i & 7;
        int tok = s_tok[row];
        uint32_t doff = SWZ((uint32_t)(row * 128 + c16 * 16));
        size_t goff = (size_t)(tok < 0 ? 0 : tok) * HD + k0 + c16 * 8;
        cp16(smem_u32(xs + doff), g_x + goff, (tok < 0) ? 0 : 16);
    }
#pragma unroll
    for (int it = 0; it < 2; it++) {
        int i = tid + it * 256;
        int row = i >> 3, c16 = i & 7;
        uint32_t doff = SWZ((uint32_t)(row * 128 + c16 * 16));
        size_t goff = ((size_t)e * ID + n0 + row) * HD + k0 + c16 * 8;
        cp16(smem_u32(w1 + doff), g_w1 + goff, 16);
        cp16(smem_u32(w3 + doff), g_w3 + goff, 16);
    }
}

__global__ __launch_bounds__(256)
void gemm1_kernel() {
    extern __shared__ char smem[];
    const int e   = blockIdx.z;
    const int cnt = g_count[e];
    const int m0  = blockIdx.y * 128;
    if (m0 >= cnt) return;
    const int n0  = blockIdx.x * 64;
    const int tid  = threadIdx.x;
    const int wid  = tid >> 5, lane = tid & 31;

    int* s_tok = (int*)smem;
    if (tid < 128) {
        int m = m0 + tid;
        s_tok[tid] = (m < cnt) ? g_tok[e * TT + m] : -1;
    }
    __syncthreads();

    const int wm = (wid & 3) * 32;
    const int wn = (wid >> 2) * 32;

    float accg[2][4][4], accu[2][4][4];
#pragma unroll
    for (int mf = 0; mf < 2; mf++)
#pragma unroll
        for (int nf = 0; nf < 4; nf++)
#pragma unroll
            for (int r = 0; r < 4; r++) { accg[mf][nf][r] = 0.f; accu[mf][nf][r] = 0.f; }

    g1_load(smem + 1024, s_tok, e, n0, 0, tid);
    CP_COMMIT();
    g1_load(smem + 1024 + STAGE_B, s_tok, e, n0, KC, tid);
    CP_COMMIT();

    const int NCH = HD / KC;   // 32
    for (int c = 0; c < NCH; c++) {
        CP_WAIT1();
        __syncthreads();   // stage c%3 ready; stage (c+2)%3 readers (iter c-1) all done

        char* sb = smem + 1024 + (c % NSTAGE) * STAGE_B;
        const uint32_t xs = smem_u32(sb);
        const uint32_t b1 = xs + 16384, b3 = xs + 24576;

#pragma unroll
        for (int kb = 0; kb < 4; kb++) {
            uint32_t af[2][4];
#pragma unroll
            for (int mf = 0; mf < 2; mf++)
                ldsm4(af[mf], xs + a_addr(wm + mf * 16, kb, lane));
            uint32_t r1[2][4], r3[2][4];
#pragma unroll
            for (int nf2 = 0; nf2 < 2; nf2++) {
                uint32_t ba = b_addr(wn + nf2 * 16, kb, lane);
                ldsm4(r1[nf2], b1 + ba);
                ldsm4(r3[nf2], b3 + ba);
            }
#pragma unroll
            for (int mf = 0; mf < 2; mf++)
#pragma unroll
                for (int nf = 0; nf < 4; nf++) {
                    const int h = nf >> 1, q = (nf & 1) * 2;
                    mma_f16(accg[mf][nf], af[mf], &r1[h][q]);
                    mma_f16(accu[mf][nf], af[mf], &r3[h][q]);
                }
        }
        if (c + 2 < NCH)
            g1_load(smem + 1024 + ((c + 2) % NSTAGE) * STAGE_B, s_tok, e, n0, (c + 2) * KC, tid);
        CP_COMMIT();
    }

    // epilogue: silu(g)*u -> fp16 act
#pragma unroll
    for (int mf = 0; mf < 2; mf++) {
#pragma unroll
        for (int rr = 0; rr < 2; rr++) {
            const int slot = m0 + wm + mf * 16 + rr * 8 + (lane >> 2);
            if (slot >= cnt) continue;
            const size_t base = (size_t)(e * TT + slot) * ID + n0;
#pragma unroll
            for (int nf = 0; nf < 4; nf++) {
                float g0 = accg[mf][nf][rr * 2 + 0], g1 = accg[mf][nf][rr * 2 + 1];
                float u0 = accu[mf][nf][rr * 2 + 0], u1 = accu[mf][nf][rr * 2 + 1];
                float a0 = u0 * g0 / (1.f + __expf(-g0));
                float a1 = u1 * g1 / (1.f + __expf(-g1));
                const int col = wn + nf * 8 + (lane & 3) * 2;
                *(__half2*)(g_act + base + col) = __floats2half2_rn(a0, a1);
            }
        }
    }
}

// ---------------- GEMM2: out[tok] += wt * (act @ w2^T) ----------------
// CTA 128(M) x 128(N); 8 warps 2x4 of 64x32.
// stage layout: a[16K] w2[16K]
__device__ __forceinline__ void g2_load(char* sb, int e, int m0, int cnt,
                                        int n0, int k0, int tid) {
    char* as = sb;
    char* ws = sb + 16384;
#pragma unroll
    for (int it = 0; it < 4; it++) {
        int i = tid + it * 256;
        int row = i >> 3, c16 = i & 7;
        uint32_t doff = SWZ((uint32_t)(row * 128 + c16 * 16));
        size_t aoff = (size_t)(e * TT + m0 + row) * ID + k0 + c16 * 8;
        cp16(smem_u32(as + doff), g_act + aoff, (m0 + row < cnt) ? 16 : 0);
        size_t woff = ((size_t)e * HD + n0 + row) * ID + k0 + c16 * 8;
        cp16(smem_u32(ws + doff), g_w2 + woff, 16);
    }
}

__global__ __launch_bounds__(256)
void gemm2_kernel(float* __restrict__ out) {
    extern __shared__ char smem[];
    const int e   = blockIdx.z;
    const int cnt = g_count[e];
    const int m0  = blockIdx.y * 128;
    if (m0 >= cnt) return;
    const int n0  = blockIdx.x * 128;
    const int tid  = threadIdx.x;
    const int wid  = tid >> 5, lane = tid & 31;

    int*   s_tok = (int*)smem;
    float* s_wt  = (float*)(smem + 512);
    if (tid < 128) {
        int m = m0 + tid;
        bool v = (m < cnt);
        s_tok[tid] = v ? g_tok[e * TT + m] : 0;
        s_wt[tid]  = v ? g_wt[e * TT + m] : 0.f;
    }
    __syncthreads();

    const int wm = (wid & 1) * 64;
    const int wn = (wid >> 1) * 32;

    float acc[4][4][4];
#pragma unroll
    for (int mf = 0; mf < 4; mf++)
#pragma unroll
        for (int nf = 0; nf < 4; nf++)
#pragma unroll
            for (int r = 0; r < 4; r++) acc[mf][nf][r] = 0.f;

    g2_load(smem + 1024, e, m0, cnt, n0, 0, tid);
    CP_COMMIT();
    g2_load(smem + 1024 + STAGE_B, e, m0, cnt, n0, KC, tid);
    CP_COMMIT();

    const int NCH = ID / KC;   // 88
    for (int c = 0; c < NCH; c++) {
        CP_WAIT1();
        __syncthreads();

        char* sb = smem + 1024 + (c % NSTAGE) * STAGE_B;
        const uint32_t ab = smem_u32(sb);
        const uint32_t wb = ab + 16384;

#pragma unroll
        for (int kb = 0; kb < 4; kb++) {
            uint32_t af[4][4];
#pragma unroll
            for (int mf = 0; mf < 4; mf++)
                ldsm4(af[mf], ab + a_addr(wm + mf * 16, kb, lane));
            uint32_t rw[2][4];
#pragma unroll
            for (int nf2 = 0; nf2 < 2; nf2++)
                ldsm4(rw[nf2], wb + b_addr(wn + nf2 * 16, kb, lane));
#pragma unroll
            for (int mf = 0; mf < 4; mf++)
#pragma unroll
                for (int nf = 0; nf < 4; nf++) {
                    const int h = nf >> 1, q = (nf & 1) * 2;
                    mma_f16(acc[mf][nf], af[mf], &rw[h][q]);
                }
        }
        if (c + 2 < NCH)
            g2_load(smem + 1024 + ((c + 2) % NSTAGE) * STAGE_B, e, m0, cnt, n0, (c + 2) * KC, tid);
        CP_COMMIT();
    }

    // epilogue: atomic weighted combine
#pragma unroll
    for (int mf = 0; mf < 4; mf++) {
#pragma unroll
        for (int rr = 0; rr < 2; rr++) {
            const int lrow = wm + mf * 16 + rr * 8 + (lane >> 2);
            if (m0 + lrow >= cnt) continue;
            const int   tok = s_tok[lrow];
            const float wt  = s_wt[lrow];
            float* op = out + (size_t)tok * HD + n0;
#pragma unroll
            for (int nf = 0; nf < 4; nf++) {
                const int col = wn + nf * 8 + (lane & 3) * 2;
                atomicAdd(op + col,     wt * acc[mf][nf][rr * 2 + 0]);
                atomicAdd(op + col + 1, wt * acc[mf][nf][rr * 2 + 1]);
            }
        }
    }
}

// ---------------- launch ----------------
extern "C" void kernel_launch(void* const* d_in, const int* in_sizes, int n_in,
                              void* d_out, int out_size) {
    const float* x  = (const float*)d_in[0];
    const float* gw = (const float*)d_in[1];
    const float* w1 = (const float*)d_in[2];
    const float* w3 = (const float*)d_in[3];
    const float* w2 = (const float*)d_in[4];
    float* out = (float*)d_out;

    static cudaStream_t s1 = nullptr;
    static cudaEvent_t ev_fork = nullptr, ev_join = nullptr;
    static bool attr_done = false;
    if (!attr_done) {
        cudaFuncSetAttribute(gemm1_kernel, cudaFuncAttributeMaxDynamicSharedMemorySize, SMEM_SZ);
        cudaFuncSetAttribute(gemm2_kernel, cudaFuncAttributeMaxDynamicSharedMemorySize, SMEM_SZ);
        cudaStreamCreateWithFlags(&s1, cudaStreamNonBlocking);
        cudaEventCreateWithFlags(&ev_fork, cudaEventDisableTiming);
        cudaEventCreateWithFlags(&ev_join, cudaEventDisableTiming);
        attr_done = true;
    }

    void *cnt_a, *x_a, *w1_a, *w3_a, *w2_a;
    cudaGetSymbolAddress(&cnt_a, g_count);
    cudaGetSymbolAddress(&x_a,  g_x);
    cudaGetSymbolAddress(&w1_a, g_w1);
    cudaGetSymbolAddress(&w3_a, g_w3);
    cudaGetSymbolAddress(&w2_a, g_w2);

    cudaMemsetAsync(cnt_a, 0, sizeof(int) * NE, 0);
    cudaMemsetAsync(d_out, 0, sizeof(float) * (size_t)out_size, 0);

    const int nw4 = (int)(WSZ / 4);
    const int nx4 = TT * HD / 4;

    // fork: cvt(w2) runs on side stream, overlapped with cvt(w1/w3)+route+gemm1
    cudaEventRecord(ev_fork, 0);
    cudaStreamWaitEvent(s1, ev_fork, 0);
    cvt_kernel<<<(nw4 + 255) / 256, 256, 0, s1>>>(w2, (__half*)w2_a, nw4);
    cudaEventRecord(ev_join, s1);

    cvt_kernel<<<(nx4 + 255) / 256, 256>>>(x,  (__half*)x_a,  nx4);
    cvt_kernel<<<(nw4 + 255) / 256, 256>>>(w1, (__half*)w1_a, nw4);
    cvt_kernel<<<(nw4 + 255) / 256, 256>>>(w3, (__half*)w3_a, nw4);

    route_kernel<<<TT, 128>>>(x, gw);

    dim3 g1(ID / 64, TT / 128, NE);    // (88, 16, 8)
    gemm1_kernel<<<g1, 256, SMEM_SZ>>>();

    // join: gemm2 needs w2
    cudaStreamWaitEvent(0, ev_join, 0);

    dim3 g2(HD / 128, TT / 128, NE);   // (16, 16, 8)
    gemm2_kernel<<<g2, 256, SMEM_SZ>>>(out);
}